// round 1
// baseline (speedup 1.0000x reference)
#include <cuda_runtime.h>
#include <math.h>

#define NB 8
#define NC 19
#define HW (512 * 512)
#define ALPHA 0.5f
#define BETA 0.5f
#define SMOOTH 1e-08f

// scratch: [0..NB*NC) = tp, [NB*NC..2*NB*NC) = sum_p, [2*NB*NC..3*NB*NC) = cnt
__device__ float g_acc[3 * NB * NC];

__global__ void zero_acc_kernel() {
    int i = blockIdx.x * blockDim.x + threadIdx.x;
    if (i < 3 * NB * NC) g_acc[i] = 0.0f;
}

__global__ __launch_bounds__(256, 2) void tversky_main_kernel(
    const float* __restrict__ pred, const int* __restrict__ target) {
    const int b = blockIdx.y;
    const float* __restrict__ p = pred + (size_t)b * NC * HW;
    const int* __restrict__ t = target + (size_t)b * HW;

    float rtp[NC], rsp[NC], rcnt[NC];
#pragma unroll
    for (int c = 0; c < NC; c++) { rtp[c] = 0.0f; rsp[c] = 0.0f; rcnt[c] = 0.0f; }

    const int stride = gridDim.x * blockDim.x;
    for (int pix = blockIdx.x * blockDim.x + threadIdx.x; pix < HW; pix += stride) {
        float e[NC];
        float m = -INFINITY;
#pragma unroll
        for (int c = 0; c < NC; c++) {
            e[c] = p[(size_t)c * HW + pix];
            m = fmaxf(m, e[c]);
        }
        float s = 0.0f;
#pragma unroll
        for (int c = 0; c < NC; c++) {
            e[c] = __expf(e[c] - m);
            s += e[c];
        }
        const float r = __fdividef(1.0f, s);
        const int tg = t[pix];
#pragma unroll
        for (int c = 0; c < NC; c++) {
            const float pc = e[c] * r;
            rsp[c] += pc;
            if (tg == c) { rtp[c] += pc; rcnt[c] += 1.0f; }
        }
    }

    // warp-level reduction of each of the 57 accumulators
#pragma unroll
    for (int c = 0; c < NC; c++) {
#pragma unroll
        for (int off = 16; off > 0; off >>= 1) {
            rtp[c]  += __shfl_down_sync(0xFFFFFFFFu, rtp[c],  off);
            rsp[c]  += __shfl_down_sync(0xFFFFFFFFu, rsp[c],  off);
            rcnt[c] += __shfl_down_sync(0xFFFFFFFFu, rcnt[c], off);
        }
    }

    __shared__ float s_acc[3 * NC];
    if (threadIdx.x < 3 * NC) s_acc[threadIdx.x] = 0.0f;
    __syncthreads();

    if ((threadIdx.x & 31) == 0) {
#pragma unroll
        for (int c = 0; c < NC; c++) {
            atomicAdd(&s_acc[c], rtp[c]);
            atomicAdd(&s_acc[NC + c], rsp[c]);
            atomicAdd(&s_acc[2 * NC + c], rcnt[c]);
        }
    }
    __syncthreads();

    // one global atomicAdd per (section, class) from first 57 threads
    if (threadIdx.x < 3 * NC) {
        const int sec = threadIdx.x / NC;
        const int c = threadIdx.x % NC;
        atomicAdd(&g_acc[sec * NB * NC + b * NC + c], s_acc[threadIdx.x]);
    }
}

__global__ void tversky_final_kernel(float* __restrict__ out) {
    __shared__ float s_red[256];
    const int i = threadIdx.x;
    float v = 0.0f;
    if (i < NB * NC) {
        const float tp = g_acc[i];
        const float sp = g_acc[NB * NC + i];
        const float cn = g_acc[2 * NB * NC + i];
        const float fp = sp - tp;
        const float fn = cn - tp;
        const float tv = (tp + SMOOTH) / (tp + ALPHA * fp + BETA * fn + SMOOTH);
        v = 1.0f - tv;
    }
    s_red[i] = v;
    __syncthreads();
#pragma unroll
    for (int off = 128; off > 0; off >>= 1) {
        if (i < off) s_red[i] += s_red[i + off];
        __syncthreads();
    }
    if (i == 0) out[0] = s_red[0] / (float)(NB * NC);
}

extern "C" void kernel_launch(void* const* d_in, const int* in_sizes, int n_in,
                              void* d_out, int out_size) {
    const float* pred = (const float*)d_in[0];
    const int* target = (const int*)d_in[1];
    float* out = (float*)d_out;

    zero_acc_kernel<<<1, 3 * NB * NC>>>();
    dim3 grid(37, NB);  // 296 blocks total = 2 per SM
    tversky_main_kernel<<<grid, 256>>>(pred, target);
    tversky_final_kernel<<<1, 256>>>(out);
}

// round 2
// speedup vs baseline: 1.2428x; 1.2428x over previous
#include <cuda_runtime.h>
#include <math.h>

#define NB 8
#define NC 19
#define HW (512 * 512)
#define HW2 (HW / 2)
#define SMOOTH 1e-08f
#define GRID_X 37
#define NBLOCKS (GRID_X * NB)
#define NTHREADS 256

// scratch: [0..152) = tp, [152..304) = sum_p, [304..456) = cnt   (NB*NC = 152)
__device__ float g_acc[3 * NB * NC];
__device__ unsigned int g_done = 0;

__global__ __launch_bounds__(NTHREADS, 2) void tversky_fused_kernel(
    const float* __restrict__ pred, const int* __restrict__ target,
    float* __restrict__ out) {
    const int b = blockIdx.y;
    const float2* __restrict__ p2 =
        (const float2*)(pred + (size_t)b * NC * HW);
    const int2* __restrict__ t2 = (const int2*)(target + (size_t)b * HW);
    const int tid = threadIdx.x;

    __shared__ float s_acc[2 * NC];   // tp, sum_p
    __shared__ int s_cnt[NC];
    __shared__ int s_is_last;
    if (tid < 2 * NC) s_acc[tid] = 0.0f;
    if (tid < NC) s_cnt[tid] = 0;
    __syncthreads();

    float rsp[NC], rtp[NC];
#pragma unroll
    for (int c = 0; c < NC; c++) { rsp[c] = 0.0f; rtp[c] = 0.0f; }

    const int stride = GRID_X * NTHREADS;
    for (int idx = blockIdx.x * NTHREADS + tid; idx < HW2; idx += stride) {
        float2 e[NC];
#pragma unroll
        for (int c = 0; c < NC; c++) e[c] = p2[(size_t)c * HW2 + idx];
        const int2 tg = t2[idx];

        float sx = 0.0f, sy = 0.0f;
#pragma unroll
        for (int c = 0; c < NC; c++) {
            e[c].x = __expf(e[c].x);
            e[c].y = __expf(e[c].y);
            sx += e[c].x;
            sy += e[c].y;
        }
        const float rx = __fdividef(1.0f, sx);
        const float ry = __fdividef(1.0f, sy);

#pragma unroll
        for (int c = 0; c < NC; c++) {
            const float px = e[c].x * rx;
            const float py = e[c].y * ry;
            rsp[c] += px + py;
            if (tg.x == c) rtp[c] += px;
            if (tg.y == c) rtp[c] += py;
        }
        atomicAdd(&s_cnt[tg.x], 1);
        atomicAdd(&s_cnt[tg.y], 1);
    }

    // warp reduce the 38 float accumulators
#pragma unroll
    for (int c = 0; c < NC; c++) {
#pragma unroll
        for (int off = 16; off > 0; off >>= 1) {
            rtp[c] += __shfl_down_sync(0xFFFFFFFFu, rtp[c], off);
            rsp[c] += __shfl_down_sync(0xFFFFFFFFu, rsp[c], off);
        }
    }
    if ((tid & 31) == 0) {
#pragma unroll
        for (int c = 0; c < NC; c++) {
            atomicAdd(&s_acc[c], rtp[c]);
            atomicAdd(&s_acc[NC + c], rsp[c]);
        }
    }
    __syncthreads();

    // block -> global (57 atomics from first 57 threads)
    if (tid < 3 * NC) {
        const int sec = tid / NC;
        const int c = tid - sec * NC;
        const float v =
            (sec == 2) ? (float)s_cnt[c] : s_acc[sec * NC + c];
        atomicAdd(&g_acc[sec * NB * NC + b * NC + c], v);
    }

    // last-block-done: the final block computes the loss and resets scratch
    __threadfence();
    if (tid == 0) {
        unsigned int n = atomicAdd(&g_done, 1u);
        s_is_last = (n == NBLOCKS - 1);
    }
    __syncthreads();
    if (!s_is_last) return;

    __shared__ float s_red[NTHREADS];
    float v = 0.0f;
    if (tid < NB * NC) {
        const float tp = __ldcg(&g_acc[tid]);
        const float sp = __ldcg(&g_acc[NB * NC + tid]);
        const float cn = __ldcg(&g_acc[2 * NB * NC + tid]);
        const float denom = tp + 0.5f * (sp - tp) + 0.5f * (cn - tp) + SMOOTH;
        v = 1.0f - (tp + SMOOTH) / denom;
    }
    s_red[tid] = v;
    __syncthreads();
#pragma unroll
    for (int off = NTHREADS / 2; off > 0; off >>= 1) {
        if (tid < off) s_red[tid] += s_red[tid + off];
        __syncthreads();
    }
    if (tid == 0) {
        out[0] = s_red[0] / (float)(NB * NC);
        g_done = 0u;
    }
    // re-zero scratch for the next graph replay (after the reads above)
    for (int i = tid; i < 3 * NB * NC; i += NTHREADS) g_acc[i] = 0.0f;
}

extern "C" void kernel_launch(void* const* d_in, const int* in_sizes, int n_in,
                              void* d_out, int out_size) {
    const float* pred = (const float*)d_in[0];
    const int* target = (const int*)d_in[1];
    float* out = (float*)d_out;

    dim3 grid(GRID_X, NB);
    tversky_fused_kernel<<<grid, NTHREADS>>>(pred, target, out);
}